// round 6
// baseline (speedup 1.0000x reference)
#include <cuda_runtime.h>

// HausdorffDTLoss: B=4, C=2, H=W=256, ALPHA=2 — bit-exact vs the reference
// 2-pass brute-force squared EDT.
// Row pass stores packed u16 *distances* (fg low16, bg high16; the half not
// matching the pixel's own bit is exactly 0; sentinel d=1023 when no opposite
// bit in the row). Column pass: exact integer min of d*d + r^2 (finite < 2^18,
// fp32-exact in the reference too; sentinel sums >= 2^20 only win when every
// row is sentinel, reproducing the reference's exact 1e9). Branchless window
// r<=4 is exact when best <= 25; rare lanes extend with an exact global scan.
//
// Single persistent kernel, 1024 blocks x 256 threads — fully co-resident
// (8 blocks/SM via __launch_bounds__(256,8)), counter grid-sync between the
// row pass and the column pass. Counters self-reset -> graph-replay safe.

#define NBLK 1024

__device__ uint2 g_pack[4][256 * 256];
__device__ float g_partial[NBLK];
__device__ unsigned g_sync1;  // zero at load; reset by last block
__device__ unsigned g_sync2;

// ---------------------------------------------------------------------------
// nearest opposite-valued bit in a 256-bit row mask
// ---------------------------------------------------------------------------
__device__ __forceinline__ int nearest_opp(const unsigned* __restrict__ w, int i,
                                           unsigned inv) {
    const int k = i >> 5, bpos = i & 31;
    unsigned m = (w[k] ^ inv) & (0xFFFFFFFFu >> (31 - bpos));
    int L = -1000000, kk = k;
    while (true) {
        if (m) { L = (kk << 5) + 31 - __clz(m); break; }
        if (--kk < 0) break;
        m = w[kk] ^ inv;
    }
    m = (w[k] ^ inv) & (0xFFFFFFFFu << bpos);
    int R = 1000000;
    kk = k;
    while (true) {
        if (m) { R = (kk << 5) + __ffs(m) - 1; break; }
        if (++kk > 7) break;
        m = w[kk] ^ inv;
    }
    return min(i - L, R - i);
}

// ---------------------------------------------------------------------------
// rare exact extension beyond the r<=4 window (global column scan)
// ---------------------------------------------------------------------------
__device__ __noinline__ unsigned extend(const uint2* __restrict__ src, int i,
                                        int col, int sh, int useY,
                                        unsigned best) {
#pragma unroll 1
    for (int r = 5; r < 256; ++r) {
        unsigned rr = (unsigned)(r * r);
        if (rr >= best) break;
        int lo = i - r, hi = i + r;
        if (lo >= 0) {
            uint2 w = __ldg(&src[lo * 256 + col]);
            unsigned d = ((useY ? w.y : w.x) >> sh) & 0xFFFFu;
            best = min(best, d * d + rr);
        }
        if (hi < 256) {
            uint2 w = __ldg(&src[hi * 256 + col]);
            unsigned d = ((useY ? w.y : w.x) >> sh) & 0xFFFFu;
            best = min(best, d * d + rr);
        }
    }
    return best;
}

// ---------------------------------------------------------------------------
// fused persistent kernel, one row (phase 1) + one 32x8 tile (phase 2) / block
// ---------------------------------------------------------------------------
__global__ __launch_bounds__(256, 8) void k_fused(const float* __restrict__ mo,
                                                  const float* __restrict__ gt,
                                                  float* __restrict__ out) {
    const int bid = blockIdx.x;
    const int t = threadIdx.x;

    __shared__ unsigned P[8], G[8];
    __shared__ uint2 tile[40 * 8];  // 2.5 KB
    __shared__ float wsum[8];
    __shared__ bool last;

    // ---------------- phase 1: row pass (1 row per block) ----------------
    {
        int b = bid >> 8, r = bid & 255;
        float m0 = mo[((b * 2 + 0) * 256 + r) * 256 + t];
        float m1 = mo[((b * 2 + 1) * 256 + r) * 256 + t];
        bool pb = (m1 > m0);  // argmax ties -> channel 0
        bool gb = (gt[(b * 256 + r) * 256 + t] > 0.5f);
        unsigned bp = __ballot_sync(0xFFFFFFFFu, pb);
        unsigned bg = __ballot_sync(0xFFFFFFFFu, gb);
        if ((t & 31) == 0) {
            P[t >> 5] = bp;
            G[t >> 5] = bg;
        }
        __syncthreads();
        int pd = nearest_opp(P, t, pb ? 0xFFFFFFFFu : 0u);
        int gd = nearest_opp(G, t, gb ? 0xFFFFFFFFu : 0u);
        unsigned ps = (pd > 255) ? 1023u : (unsigned)pd;
        unsigned gs = (gd > 255) ? 1023u : (unsigned)gd;
        uint2 o;
        o.x = pb ? ps : (ps << 16);  // fg dist low16, bg dist high16 (other = 0)
        o.y = gb ? gs : (gs << 16);
        g_pack[b][r * 256 + t] = o;
    }

    // ---------------- grid sync ----------------
    __threadfence();
    __syncthreads();
    if (t == 0) {
        atomicAdd(&g_sync1, 1u);
        while (*((volatile unsigned*)&g_sync1) < NBLK) __nanosleep(32);
    }
    __syncthreads();
    __threadfence();

    // ---------------- phase 2: column pass + loss (1 tile per block) -------
    float acc;
    {
        int b = bid >> 8, ry = (bid >> 5) & 7, cg = bid & 31;
        int base = ry * 32 - 4;
        const uint2* src = g_pack[b];

        {  // load 40x8 tile (halo rows = fake sentinel, never win)
            int trow = t >> 3, c2 = t & 7, grow = base + trow;
            tile[t] = ((unsigned)grow < 256u) ? src[grow * 256 + cg * 8 + c2]
                                              : make_uint2(0x03FF03FFu, 0x03FF03FFu);
            if (t < 64) {
                int idx2 = t + 256;
                int trow2 = idx2 >> 3, c22 = idx2 & 7, grow2 = base + trow2;
                tile[idx2] = ((unsigned)grow2 < 256u)
                                 ? src[grow2 * 256 + cg * 8 + c22]
                                 : make_uint2(0x03FF03FFu, 0x03FF03FFu);
            }
        }
        __syncthreads();

        int c = t & 7;
        int ti = (t >> 3) + 4;
        int i = ry * 32 + (t >> 3);
        int col = cg * 8 + c;
        const uint2* tcol = tile + c;

        uint2 v = tcol[ti * 8];
        bool pbit = (v.x & 0xFFFFu) != 0u;  // own-plane dist >= 1 iff bit set
        bool gbit = (v.y & 0xFFFFu) != 0u;
        int shp = pbit ? 0 : 16;
        int shg = gbit ? 0 : 16;

        unsigned bestP = 0xFFFFFFFFu, bestG = 0xFFFFFFFFu;
#pragma unroll
        for (int dr = -4; dr <= 4; ++dr) {
            uint2 w = tcol[(ti + dr) * 8];
            unsigned rr = (unsigned)(dr * dr);
            unsigned dp = (w.x >> shp) & 0xFFFFu;
            unsigned dg = (w.y >> shg) & 0xFFFFu;
            bestP = min(bestP, dp * dp + rr);
            bestG = min(bestG, dg * dg + rr);
        }
        if (bestP > 25u) bestP = extend(src, i, col, shp, 0, bestP);
        if (bestG > 25u) bestG = extend(src, i, col, shg, 1, bestG);

        float e = (pbit != gbit) ? 1.0f : 0.0f;
        float Dp = (bestP >= (1u << 20)) ? 1.0e9f : (float)bestP;
        float sp = sqrtf(Dp);
        float pterm = sp * sp;  // fl(sqrt(D)^2): matches reference rounding
        if (!pbit && bestP >= (1u << 20)) pterm = 0.0f;  // fg-empty guard
        float Dg = (bestG >= (1u << 20)) ? 1.0e9f : (float)bestG;
        float sg = sqrtf(Dg);
        float gterm = sg * sg;
        if (!gbit && bestG >= (1u << 20)) gterm = 0.0f;
        acc = e * (pterm + gterm);
    }

    // ---------------- block reduction + last-block finalize ----------------
#pragma unroll
    for (int o = 16; o > 0; o >>= 1) acc += __shfl_down_sync(0xFFFFFFFFu, acc, o);
    if ((t & 31) == 0) wsum[t >> 5] = acc;
    __syncthreads();
    if (t == 0) {
        float s = 0.0f;
#pragma unroll
        for (int j = 0; j < 8; ++j) s += wsum[j];
        g_partial[bid] = s;
        __threadfence();
        last = (atomicAdd(&g_sync2, 1u) == NBLK - 1);
    }
    __syncthreads();
    if (last) {
        __threadfence();
        float s = g_partial[t] + g_partial[t + 256] + g_partial[t + 512] +
                  g_partial[t + 768];
#pragma unroll
        for (int o = 16; o > 0; o >>= 1) s += __shfl_down_sync(0xFFFFFFFFu, s, o);
        if ((t & 31) == 0) wsum[t >> 5] = s;
        __syncthreads();
        if (t == 0) {
            float tot = 0.0f;
#pragma unroll
            for (int j = 0; j < 8; ++j) tot += wsum[j];
            out[0] = tot * (1.0f / 262144.0f);
            g_sync1 = 0;  // reset for next graph replay
            g_sync2 = 0;
        }
    }
}

extern "C" void kernel_launch(void* const* d_in, const int* in_sizes, int n_in,
                              void* d_out, int out_size) {
    const float* mo = (const float*)d_in[0];  // model_output (4,2,256,256) f32
    const float* gt = (const float*)d_in[1];  // ground_truth (4,1,256,256) f32
    float* out = (float*)d_out;

    k_fused<<<NBLK, 256>>>(mo, gt, out);
}

// round 7
// speedup vs baseline: 1.2328x; 1.2328x over previous
#include <cuda_runtime.h>

// HausdorffDTLoss: B=4, C=2, H=W=256, ALPHA=2 — bit-exact vs the reference
// 2-pass brute-force squared EDT.
// Row pass stores packed u16 *distances* (fg low16, bg high16; the half not
// matching the pixel's own bit is exactly 0; sentinel d=1023 when no opposite
// bit in the row). Column pass: exact integer min of d*d + r^2 (finite < 2^18,
// fp32-exact in the reference too; sentinel sums >= 2^20 only win when every
// row is sentinel, reproducing the reference's exact 1e9 result). Branchless
// window r<=4 is exact when best <= 25 (any r>=5 candidate >= 25); rare lanes
// extend with an exact global column scan.

#define HH 256
#define WW 256
#define BB 4

__device__ uint2 g_pack[BB][HH * WW];
__device__ float g_partial[1024];
__device__ unsigned g_count;  // zero at load; last block resets -> replay-safe

// ---------------------------------------------------------------------------
// nearest opposite-valued bit in a 256-bit row mask
// ---------------------------------------------------------------------------
__device__ __forceinline__ int nearest_opp(const unsigned* __restrict__ w, int i,
                                           unsigned inv) {
    const int k = i >> 5, bpos = i & 31;
    unsigned m = (w[k] ^ inv) & (0xFFFFFFFFu >> (31 - bpos));
    int L = -1000000, kk = k;
    while (true) {
        if (m) { L = (kk << 5) + 31 - __clz(m); break; }
        if (--kk < 0) break;
        m = w[kk] ^ inv;
    }
    m = (w[k] ^ inv) & (0xFFFFFFFFu << bpos);
    int R = 1000000;
    kk = k;
    while (true) {
        if (m) { R = (kk << 5) + __ffs(m) - 1; break; }
        if (++kk > 7) break;
        m = w[kk] ^ inv;
    }
    return min(i - L, R - i);
}

// ---------------------------------------------------------------------------
// K1: row pass. grid=(256 rows, 4 batches), block=256. One STG.64 per pixel.
// ---------------------------------------------------------------------------
__global__ __launch_bounds__(256) void k_rowpass(const float* __restrict__ mo,
                                                 const float* __restrict__ gt) {
    const int r = blockIdx.x;
    const int b = blockIdx.y;
    const int t = threadIdx.x;

    __shared__ unsigned P[8], G[8];

    float m0 = mo[((b * 2 + 0) * HH + r) * WW + t];
    float m1 = mo[((b * 2 + 1) * HH + r) * WW + t];
    bool pb = (m1 > m0);  // argmax ties -> channel 0
    bool gb = (gt[(b * HH + r) * WW + t] > 0.5f);

    unsigned bp = __ballot_sync(0xFFFFFFFFu, pb);
    unsigned bg = __ballot_sync(0xFFFFFFFFu, gb);
    if ((t & 31) == 0) {
        P[t >> 5] = bp;
        G[t >> 5] = bg;
    }
    __syncthreads();

    int pd = nearest_opp(P, t, pb ? 0xFFFFFFFFu : 0u);
    int gd = nearest_opp(G, t, gb ? 0xFFFFFFFFu : 0u);
    unsigned ps = (pd > 255) ? 1023u : (unsigned)pd;
    unsigned gs = (gd > 255) ? 1023u : (unsigned)gd;
    uint2 o;
    o.x = pb ? ps : (ps << 16);  // fg dist low16, bg dist high16 (other = 0)
    o.y = gb ? gs : (gs << 16);
    g_pack[b][r * WW + t] = o;
}

// ---------------------------------------------------------------------------
// rare exact extension beyond the r<=4 window (global column scan)
// ---------------------------------------------------------------------------
__device__ __noinline__ unsigned extend(const uint2* __restrict__ src, int i,
                                        int col, int sh, int useY,
                                        unsigned best) {
#pragma unroll 1
    for (int r = 5; r < 256; ++r) {
        unsigned rr = (unsigned)(r * r);
        if (rr >= best) break;
        int lo = i - r, hi = i + r;
        if (lo >= 0) {
            uint2 w = __ldg(&src[lo * WW + col]);
            unsigned d = ((useY ? w.y : w.x) >> sh) & 0xFFFFu;
            best = min(best, d * d + rr);
        }
        if (hi < 256) {
            uint2 w = __ldg(&src[hi * WW + col]);
            unsigned d = ((useY ? w.y : w.x) >> sh) & 0xFFFFu;
            best = min(best, d * d + rr);
        }
    }
    return best;
}

// ---------------------------------------------------------------------------
// K2: column pass + fused loss + last-block finalize.
// grid=(32 colgroups, 8 rowtiles, 4 batches), block=256: one thread per pixel.
// ---------------------------------------------------------------------------
__global__ __launch_bounds__(256) void k_colpass(float* __restrict__ out) {
    const int cg = blockIdx.x;
    const int ry = blockIdx.y;
    const int b = blockIdx.z;
    const int t = threadIdx.x;
    const int base = ry * 32 - 4;

    __shared__ uint2 tile[40 * 8];  // 2.5 KB
    __shared__ float wsum[8];
    __shared__ bool last;

    const uint2* src = g_pack[b];
    {  // load 40x8 tile (halo rows = fake sentinel, never win)
        int trow = t >> 3, c2 = t & 7, grow = base + trow;
        tile[t] = ((unsigned)grow < 256u) ? src[grow * WW + cg * 8 + c2]
                                          : make_uint2(0x03FF03FFu, 0x03FF03FFu);
        if (t < 64) {
            int idx2 = t + 256;
            int trow2 = idx2 >> 3, c22 = idx2 & 7, grow2 = base + trow2;
            tile[idx2] = ((unsigned)grow2 < 256u)
                             ? src[grow2 * WW + cg * 8 + c22]
                             : make_uint2(0x03FF03FFu, 0x03FF03FFu);
        }
    }
    __syncthreads();

    const int c = t & 7;
    const int ti = (t >> 3) + 4;
    const int i = ry * 32 + (t >> 3);
    const int col = cg * 8 + c;
    const uint2* tcol = tile + c;

    uint2 v = tcol[ti * 8];
    bool pbit = (v.x & 0xFFFFu) != 0u;  // own-plane dist >= 1 iff bit set
    bool gbit = (v.y & 0xFFFFu) != 0u;
    int shp = pbit ? 0 : 16;
    int shg = gbit ? 0 : 16;

    unsigned bestP = 0xFFFFFFFFu, bestG = 0xFFFFFFFFu;
#pragma unroll
    for (int dr = -4; dr <= 4; ++dr) {
        uint2 w = tcol[(ti + dr) * 8];
        unsigned rr = (unsigned)(dr * dr);
        unsigned dp = (w.x >> shp) & 0xFFFFu;
        unsigned dg = (w.y >> shg) & 0xFFFFu;
        bestP = min(bestP, dp * dp + rr);
        bestG = min(bestG, dg * dg + rr);
    }
    if (bestP > 25u) bestP = extend(src, i, col, shp, 0, bestP);
    if (bestG > 25u) bestG = extend(src, i, col, shg, 1, bestG);

    float e = (pbit != gbit) ? 1.0f : 0.0f;
    float Dp = (bestP >= (1u << 20)) ? 1.0e9f : (float)bestP;
    float sp = sqrtf(Dp);
    float pterm = sp * sp;  // fl(sqrt(D)^2): matches reference rounding
    if (!pbit && bestP >= (1u << 20)) pterm = 0.0f;  // fg-empty guard
    float Dg = (bestG >= (1u << 20)) ? 1.0e9f : (float)bestG;
    float sg = sqrtf(Dg);
    float gterm = sg * sg;
    if (!gbit && bestG >= (1u << 20)) gterm = 0.0f;
    float acc = e * (pterm + gterm);

    // deterministic block reduction
#pragma unroll
    for (int o = 16; o > 0; o >>= 1) acc += __shfl_down_sync(0xFFFFFFFFu, acc, o);
    if ((t & 31) == 0) wsum[t >> 5] = acc;
    __syncthreads();
    if (t == 0) {
        float s = 0.0f;
#pragma unroll
        for (int j = 0; j < 8; ++j) s += wsum[j];
        g_partial[((b * 8 + ry) * 32) + cg] = s;
        __threadfence();
        last = (atomicAdd(&g_count, 1u) == 1023u);
    }
    __syncthreads();
    if (last) {
        __threadfence();
        float s = g_partial[t] + g_partial[t + 256] + g_partial[t + 512] +
                  g_partial[t + 768];
#pragma unroll
        for (int o = 16; o > 0; o >>= 1) s += __shfl_down_sync(0xFFFFFFFFu, s, o);
        if ((t & 31) == 0) wsum[t >> 5] = s;
        __syncthreads();
        if (t == 0) {
            float tot = 0.0f;
#pragma unroll
            for (int j = 0; j < 8; ++j) tot += wsum[j];
            out[0] = tot * (1.0f / 262144.0f);
            g_count = 0;  // reset for next graph replay
        }
    }
}

extern "C" void kernel_launch(void* const* d_in, const int* in_sizes, int n_in,
                              void* d_out, int out_size) {
    const float* mo = (const float*)d_in[0];  // model_output (4,2,256,256) f32
    const float* gt = (const float*)d_in[1];  // ground_truth (4,1,256,256) f32
    float* out = (float*)d_out;

    dim3 grid1(HH, BB);
    k_rowpass<<<grid1, 256>>>(mo, gt);
    dim3 grid2(32, 8, BB);
    k_colpass<<<grid2, 256>>>(out);
}

// round 8
// speedup vs baseline: 1.5015x; 1.2179x over previous
#include <cuda_runtime.h>

// HausdorffDTLoss: B=4, C=2, H=W=256, ALPHA=2 — matches the reference 2-pass
// brute-force squared EDT exactly (up to final-sum association):
//  - row pass stores packed u16 nearest-opposite-bit distances (fg low16,
//    bg high16; the half not matching the pixel's own bit is exactly 0;
//    sentinel d=1024 when the row has no opposite bit, 1024^2 = 2^20).
//  - column pass: exact integer min of d*d + r^2 (finite < 2^18, fp32-exact
//    ints in the reference too; sentinel sums >= 2^20 only win when every row
//    is sentinel, reproducing the reference's exact 1e9). Branchless window
//    r<=4 is exact when best <= 25; rare lanes do an exact global column scan.
// Grids sized for a SINGLE co-resident wave (512 blocks x 8 warps = 4096
// warps <= 148*32). Final sum via one REDG atomicAdd per block (out zeroed by
// the row pass; stream order makes that safe under graph replay).

#define HH 256
#define WW 256
#define BB 4
#define SENT 1024u
#define SENTP 0x04000400u

__device__ uint2 g_pack[BB][HH * WW];

// ---------------------------------------------------------------------------
// nearest opposite-valued bit in a 256-bit row mask
// ---------------------------------------------------------------------------
__device__ __forceinline__ int nearest_opp(const unsigned* __restrict__ w, int i,
                                           unsigned inv) {
    const int k = i >> 5, bpos = i & 31;
    unsigned m = (w[k] ^ inv) & (0xFFFFFFFFu >> (31 - bpos));
    int L = -1000000, kk = k;
    while (true) {
        if (m) { L = (kk << 5) + 31 - __clz(m); break; }
        if (--kk < 0) break;
        m = w[kk] ^ inv;
    }
    m = (w[k] ^ inv) & (0xFFFFFFFFu << bpos);
    int R = 1000000;
    kk = k;
    while (true) {
        if (m) { R = (kk << 5) + __ffs(m) - 1; break; }
        if (++kk > 7) break;
        m = w[kk] ^ inv;
    }
    return min(i - L, R - i);
}

// ---------------------------------------------------------------------------
// K1: row pass, 2 rows per block. grid=(128, 4), block=256. Also zeroes out.
// ---------------------------------------------------------------------------
__global__ __launch_bounds__(256) void k_rowpass(const float* __restrict__ mo,
                                                 const float* __restrict__ gt,
                                                 float* __restrict__ out) {
    const int rp = blockIdx.x;  // row pair
    const int b = blockIdx.y;
    const int t = threadIdx.x;

    __shared__ unsigned P[2][8], G[2][8];
    bool pb[2], gb[2];

#pragma unroll
    for (int k = 0; k < 2; ++k) {
        int r = rp * 2 + k;
        float m0 = mo[((b * 2 + 0) * HH + r) * WW + t];
        float m1 = mo[((b * 2 + 1) * HH + r) * WW + t];
        pb[k] = (m1 > m0);  // argmax ties -> channel 0
        gb[k] = (gt[(b * HH + r) * WW + t] > 0.5f);
        unsigned bp = __ballot_sync(0xFFFFFFFFu, pb[k]);
        unsigned bg = __ballot_sync(0xFFFFFFFFu, gb[k]);
        if ((t & 31) == 0) {
            P[k][t >> 5] = bp;
            G[k][t >> 5] = bg;
        }
    }
    __syncthreads();

#pragma unroll
    for (int k = 0; k < 2; ++k) {
        int r = rp * 2 + k;
        int pd = nearest_opp(P[k], t, pb[k] ? 0xFFFFFFFFu : 0u);
        int gd = nearest_opp(G[k], t, gb[k] ? 0xFFFFFFFFu : 0u);
        unsigned ps = (pd > 255) ? SENT : (unsigned)pd;
        unsigned gs = (gd > 255) ? SENT : (unsigned)gd;
        uint2 o;
        o.x = pb[k] ? ps : (ps << 16);  // fg dist low16, bg dist high16
        o.y = gb[k] ? gs : (gs << 16);
        g_pack[b][r * WW + t] = o;
    }

    if (rp == 0 && b == 0 && t == 0) out[0] = 0.0f;
}

// ---------------------------------------------------------------------------
// rare exact extension beyond the r<=4 window (global column scan)
// ---------------------------------------------------------------------------
__device__ __noinline__ unsigned extend(const uint2* __restrict__ src, int i,
                                        int col, int sh, int useY,
                                        unsigned best) {
#pragma unroll 1
    for (int r = 5; r < 256; ++r) {
        unsigned rr = (unsigned)(r * r);
        if (rr >= best) break;
        int lo = i - r, hi = i + r;
        if (lo >= 0) {
            uint2 w = __ldg(&src[lo * WW + col]);
            unsigned d = ((useY ? w.y : w.x) >> sh) & 0xFFFFu;
            best = min(best, d * d + rr);
        }
        if (hi < 256) {
            uint2 w = __ldg(&src[hi * WW + col]);
            unsigned d = ((useY ? w.y : w.x) >> sh) & 0xFFFFu;
            best = min(best, d * d + rr);
        }
    }
    return best;
}

// ---------------------------------------------------------------------------
// per-pixel loss term from the column tile
// ---------------------------------------------------------------------------
__device__ __forceinline__ float pixel_term(const uint2* __restrict__ tcol,
                                            int ti, const uint2* __restrict__ src,
                                            int i, int col) {
    uint2 v = tcol[ti * 16];
    bool pbit = (v.x & 0xFFFFu) != 0u;  // own-plane dist >= 1 iff bit set
    bool gbit = (v.y & 0xFFFFu) != 0u;
    int shp = pbit ? 0 : 16;
    int shg = gbit ? 0 : 16;

    unsigned bestP = 0xFFFFFFFFu, bestG = 0xFFFFFFFFu;
#pragma unroll
    for (int dr = -4; dr <= 4; ++dr) {
        uint2 w = tcol[(ti + dr) * 16];
        unsigned rr = (unsigned)(dr * dr);
        unsigned dp = (w.x >> shp) & 0xFFFFu;
        unsigned dg = (w.y >> shg) & 0xFFFFu;
        bestP = min(bestP, dp * dp + rr);
        bestG = min(bestG, dg * dg + rr);
    }
    if (bestP > 25u) bestP = extend(src, i, col, shp, 0, bestP);
    if (bestG > 25u) bestG = extend(src, i, col, shg, 1, bestG);

    float e = (pbit != gbit) ? 1.0f : 0.0f;
    float Dp = (bestP >= (1u << 20)) ? 1.0e9f : (float)bestP;
    float sp = sqrtf(Dp);
    float pterm = sp * sp;  // fl(sqrt(D)^2): matches reference rounding
    if (!pbit && bestP >= (1u << 20)) pterm = 0.0f;  // fg-empty guard
    float Dg = (bestG >= (1u << 20)) ? 1.0e9f : (float)bestG;
    float sg = sqrtf(Dg);
    float gterm = sg * sg;
    if (!gbit && bestG >= (1u << 20)) gterm = 0.0f;
    return e * (pterm + gterm);
}

// ---------------------------------------------------------------------------
// K2: column pass + fused loss. grid=(16 colgroups, 8 rowtiles, 4 batches)
// = 512 blocks (single wave), block=256, 32x16 tile (2 px/thread).
// ---------------------------------------------------------------------------
__global__ __launch_bounds__(256) void k_colpass(float* __restrict__ out) {
    const int cg = blockIdx.x;  // 16-col group
    const int ry = blockIdx.y;
    const int b = blockIdx.z;
    const int t = threadIdx.x;
    const int base = ry * 32 - 4;

    __shared__ uint2 tile[40 * 16];  // 5 KB
    __shared__ float wsum[8];

    const uint2* src = g_pack[b];
#pragma unroll
    for (int idx = t; idx < 640; idx += 256) {
        int grow = base + (idx >> 4), c2 = idx & 15;
        tile[idx] = ((unsigned)grow < 256u) ? src[grow * WW + cg * 16 + c2]
                                            : make_uint2(SENTP, SENTP);
    }
    __syncthreads();

    const int c = t & 15;
    const int rb = t >> 4;  // 0..15
    const int col = cg * 16 + c;
    const uint2* tcol = tile + c;

    float acc = pixel_term(tcol, rb + 4, src, ry * 32 + rb, col) +
                pixel_term(tcol, rb + 20, src, ry * 32 + rb + 16, col);

    // deterministic block reduction, then one REDG add of the scaled partial
#pragma unroll
    for (int o = 16; o > 0; o >>= 1) acc += __shfl_down_sync(0xFFFFFFFFu, acc, o);
    if ((t & 31) == 0) wsum[t >> 5] = acc;
    __syncthreads();
    if (t == 0) {
        float s = 0.0f;
#pragma unroll
        for (int j = 0; j < 8; ++j) s += wsum[j];
        atomicAdd(out, s * (1.0f / 262144.0f));
    }
}

extern "C" void kernel_launch(void* const* d_in, const int* in_sizes, int n_in,
                              void* d_out, int out_size) {
    const float* mo = (const float*)d_in[0];  // model_output (4,2,256,256) f32
    const float* gt = (const float*)d_in[1];  // ground_truth (4,1,256,256) f32
    float* out = (float*)d_out;

    dim3 grid1(128, BB);
    k_rowpass<<<grid1, 256>>>(mo, gt, out);
    dim3 grid2(16, 8, BB);
    k_colpass<<<grid2, 256>>>(out);
}